// round 10
// baseline (speedup 1.0000x reference)
#include <cuda_runtime.h>
#include <cuda_bf16.h>
#include <math.h>
#include <stdint.h>

// Problem constants
#define BATCH 256
#define HD    256
#define G4    1024
#define TSTEPS 512
#define OUTD  702
#define OUTP  704           // padded to 11*64

#define NBG 16
#define NSL 8
#define BB  16
#define RGRID (NBG*NSL)     // 128
#define RTHREADS 256

#define REC_ELEMS ((size_t)BATCH*TSTEPS*OUTD)

// proj tiling
#define MROWS (BATCH*TSTEPS)            // 131072
#define MT    128
#define NT    64
#define NMT   (MROWS/MT)                // 1024
#define NNT   (OUTP/NT)                 // 11

#define GFS   132                       // gfin/cns padded stride
#define HSS   264                       // smem h padded stride (bf16)

// -------- device scratch (no allocations allowed) --------
__device__ __align__(16) float g_const[BATCH * G4];
__device__ int g_done[RGRID];
// ping-pong split-bf16 hidden state for the recurrence
__device__ __align__(16) __nv_bfloat16 g_hsp_hi[2][BATCH * HD];
__device__ __align__(16) __nv_bfloat16 g_hsp_lo[2][BATCH * HD];
// split-bf16 row-major images for the MMA projection
__device__ __align__(16) __nv_bfloat16 g_Ahi[(size_t)MROWS * HD];   // 64MB
__device__ __align__(16) __nv_bfloat16 g_Alo[(size_t)MROWS * HD];   // 64MB
__device__ __align__(16) __nv_bfloat16 g_Bhi[(size_t)OUTP * HD];
__device__ __align__(16) __nv_bfloat16 g_Blo[(size_t)OUTP * HD];

__device__ __forceinline__ float fast_tanh(float x) {
    float y;
    asm("tanh.approx.f32 %0, %1;" : "=f"(y) : "f"(x));
    return y;
}
__device__ __forceinline__ float fast_sig(float x) {
    return fmaf(fast_tanh(0.5f * x), 0.5f, 0.5f);
}
__device__ __forceinline__ void split_bf2(float x, float y, uint32_t& hi, uint32_t& lo) {
    __nv_bfloat16 xh = __float2bfloat16(x);
    __nv_bfloat16 yh = __float2bfloat16(y);
    __nv_bfloat16 xl = __float2bfloat16(x - __bfloat162float(xh));
    __nv_bfloat16 yl = __float2bfloat16(y - __bfloat162float(yh));
    __nv_bfloat162 ph; ph.x = xh; ph.y = yh;
    __nv_bfloat162 pl; pl.x = xl; pl.y = yl;
    hi = *(uint32_t*)&ph;
    lo = *(uint32_t*)&pl;
}

__device__ __forceinline__ void mma16816(float* c, const uint32_t* a, const uint32_t* b) {
    asm volatile(
        "mma.sync.aligned.m16n8k16.row.col.f32.bf16.bf16.f32 "
        "{%0,%1,%2,%3}, {%4,%5,%6,%7}, {%8,%9}, {%0,%1,%2,%3};"
        : "+f"(c[0]), "+f"(c[1]), "+f"(c[2]), "+f"(c[3])
        : "r"(a[0]), "r"(a[1]), "r"(a[2]), "r"(a[3]), "r"(b[0]), "r"(b[1]));
}
__device__ __forceinline__ void mma16816b(float* c, const uint32_t* a, uint32_t b0, uint32_t b1) {
    asm volatile(
        "mma.sync.aligned.m16n8k16.row.col.f32.bf16.bf16.f32 "
        "{%0,%1,%2,%3}, {%4,%5,%6,%7}, {%8,%9}, {%0,%1,%2,%3};"
        : "+f"(c[0]), "+f"(c[1]), "+f"(c[2]), "+f"(c[3])
        : "r"(a[0]), "r"(a[1]), "r"(a[2]), "r"(a[3]), "r"(b0), "r"(b1));
}

// ============================================================
// Kernel 1: precompute const gates (tiled GEMM) + reset flags
// ============================================================
__global__ void precompute_kernel(const float* __restrict__ embed,
                                  const float* __restrict__ W_ih,
                                  const float* __restrict__ b_ih,
                                  const float* __restrict__ b_hh) {
    __shared__ float As[16][64];
    __shared__ float Bs[16][64];
    const int tid = threadIdx.x;
    if (blockIdx.x == 0 && blockIdx.y == 0 && tid < RGRID) g_done[tid] = 0;

    const int m0 = blockIdx.x * 64;
    const int n0 = blockIdx.y * 64;
    const int tx = tid & 15, ty = tid >> 4;
    const int lm = tid >> 2;
    const int lk = (tid & 3) * 4;

    float acc[4][4];
#pragma unroll
    for (int i = 0; i < 4; ++i)
#pragma unroll
        for (int j = 0; j < 4; ++j) acc[i][j] = 0.f;

    for (int k0 = 0; k0 < HD; k0 += 16) {
        float4 av = *(const float4*)&embed[(size_t)(m0 + lm) * HD + k0 + lk];
        float4 bv = *(const float4*)&W_ih[(size_t)(n0 + lm) * HD + k0 + lk];
        As[lk + 0][lm] = av.x; As[lk + 1][lm] = av.y;
        As[lk + 2][lm] = av.z; As[lk + 3][lm] = av.w;
        Bs[lk + 0][lm] = bv.x; Bs[lk + 1][lm] = bv.y;
        Bs[lk + 2][lm] = bv.z; Bs[lk + 3][lm] = bv.w;
        __syncthreads();
#pragma unroll
        for (int k = 0; k < 16; ++k) {
            float4 a = *(const float4*)&As[k][ty * 4];
            float4 b = *(const float4*)&Bs[k][tx * 4];
            acc[0][0] = fmaf(a.x, b.x, acc[0][0]); acc[0][1] = fmaf(a.x, b.y, acc[0][1]);
            acc[0][2] = fmaf(a.x, b.z, acc[0][2]); acc[0][3] = fmaf(a.x, b.w, acc[0][3]);
            acc[1][0] = fmaf(a.y, b.x, acc[1][0]); acc[1][1] = fmaf(a.y, b.y, acc[1][1]);
            acc[1][2] = fmaf(a.y, b.z, acc[1][2]); acc[1][3] = fmaf(a.y, b.w, acc[1][3]);
            acc[2][0] = fmaf(a.z, b.x, acc[2][0]); acc[2][1] = fmaf(a.z, b.y, acc[2][1]);
            acc[2][2] = fmaf(a.z, b.z, acc[2][2]); acc[2][3] = fmaf(a.z, b.w, acc[2][3]);
            acc[3][0] = fmaf(a.w, b.x, acc[3][0]); acc[3][1] = fmaf(a.w, b.y, acc[3][1]);
            acc[3][2] = fmaf(a.w, b.z, acc[3][2]); acc[3][3] = fmaf(a.w, b.w, acc[3][3]);
        }
        __syncthreads();
    }
#pragma unroll
    for (int i = 0; i < 4; ++i) {
        int b = m0 + ty * 4 + i;
#pragma unroll
        for (int j = 0; j < 4; ++j) {
            int row = n0 + tx * 4 + j;
            g_const[(size_t)b * G4 + row] = acc[i][j] + b_ih[row] + b_hh[row];
        }
    }
}

// ============================================================
// Kernel 1b: W_rec -> split-bf16 row-major images
// ============================================================
__global__ void convert_wrec_kernel(const float* __restrict__ Wr) {
    int n = blockIdx.x;
    int k = threadIdx.x;
    float v = (n < OUTD) ? Wr[(size_t)n * HD + k] : 0.f;
    __nv_bfloat16 hi = __float2bfloat16(v);
    __nv_bfloat16 lo = __float2bfloat16(v - __bfloat162float(hi));
    g_Bhi[(size_t)n * HD + k] = hi;
    g_Blo[(size_t)n * HD + k] = lo;
}

// ============================================================
// Kernel 2: persistent LSTM recurrence on tensor cores
// 3 SEPARATE product accumulators -> 6 independent MMA chains
// ============================================================
__global__ void __launch_bounds__(RTHREADS, 1)
lstm_kernel(const float* __restrict__ W_ih,
            const float* __restrict__ W_hh,
            float* __restrict__ dec_out) {
    const int bg  = blockIdx.x >> 3;
    const int sl  = blockIdx.x & 7;
    const int tid = threadIdx.x;
    const int wid = tid >> 5;
    const int lid = tid & 31;

    __shared__ __align__(16) __nv_bfloat16 h_hi[BB * HSS];
    __shared__ __align__(16) __nv_bfloat16 h_lo[BB * HSS];
    __shared__ float gfin[BB * GFS];
    __shared__ float cns[BB * GFS];

    // ---- weight A-fragments in registers ----
    const int gg = lid >> 2;
    const int t2 = (lid & 3) * 2;
    uint32_t wahi[16][4], walo[16][4];
    {
        const int lr[2] = { wid * 16 + gg, wid * 16 + gg + 8 };
        int grow[2];
#pragma unroll
        for (int rr = 0; rr < 2; ++rr)
            grow[rr] = (lr[rr] >> 5) * 256 + sl * 32 + (lr[rr] & 31);
#pragma unroll
        for (int k16 = 0; k16 < 16; ++k16) {
#pragma unroll
            for (int kk = 0; kk < 2; ++kk) {
                int col = k16 * 16 + t2 + kk * 8;
#pragma unroll
                for (int rr = 0; rr < 2; ++rr) {
                    float2 a = *(const float2*)&W_ih[(size_t)grow[rr] * HD + col];
                    float2 b = *(const float2*)&W_hh[(size_t)grow[rr] * HD + col];
                    split_bf2(a.x + b.x, a.y + b.y,
                              wahi[k16][kk * 2 + rr], walo[k16][kk * 2 + rr]);
                }
            }
        }
    }

    for (int idx = tid; idx < BB * 128; idx += RTHREADS) {
        int b  = idx >> 7;
        int rr = idx & 127;
        int gr = (rr >> 5) * 256 + sl * 32 + (rr & 31);
        cns[b * GFS + rr] = g_const[(bg * BB + b) * G4 + gr];
    }

    const int ub = tid >> 4;
    const int cc = (tid & 15) * 2;
    const int brow = bg * BB + ub;
    const int col0 = sl * 32 + cc;
    float c0 = 0.f, c1 = 0.f;

    __syncthreads();

    for (int t = 0; t < TSTEPS; ++t) {
        // ---- stage h_{t-1} split-bf16 into padded smem ----
        if (t == 0) {
            for (int idx = tid; idx < (BB * HSS * 2) / 16; idx += RTHREADS) {
                ((uint4*)h_hi)[idx] = make_uint4(0, 0, 0, 0);
                ((uint4*)h_lo)[idx] = make_uint4(0, 0, 0, 0);
            }
        } else {
            const uint4* shi = (const uint4*)&g_hsp_hi[t & 1][bg * BB * HD];
            const uint4* slo = (const uint4*)&g_hsp_lo[t & 1][bg * BB * HD];
#pragma unroll
            for (int i = 0; i < 2; ++i) {
                int idx = tid + i * RTHREADS;
                int batch = idx >> 5, ch = idx & 31;
                uint4 vh = __ldcg(&shi[idx]);
                uint4 vl = __ldcg(&slo[idx]);
                *(uint4*)&h_hi[batch * HSS + ch * 8] = vh;
                *(uint4*)&h_lo[batch * HSS + ch * 8] = vl;
            }
        }
        __syncthreads();

        // ---- tensor-core gates: 3 separate product accumulators ----
        float acc[3][2][4];
#pragma unroll
        for (int p = 0; p < 3; ++p)
#pragma unroll
            for (int nt = 0; nt < 2; ++nt)
#pragma unroll
                for (int q = 0; q < 4; ++q) acc[p][nt][q] = 0.f;

#pragma unroll
        for (int k16 = 0; k16 < 16; ++k16) {
            const int k0 = k16 * 16 + t2;
            uint32_t bh0[2], bh1[2], bl0[2], bl1[2];
#pragma unroll
            for (int nt = 0; nt < 2; ++nt) {
                const int n = nt * 8 + gg;
                bh0[nt] = *(const uint32_t*)&h_hi[n * HSS + k0];
                bh1[nt] = *(const uint32_t*)&h_hi[n * HSS + k0 + 8];
                bl0[nt] = *(const uint32_t*)&h_lo[n * HSS + k0];
                bl1[nt] = *(const uint32_t*)&h_lo[n * HSS + k0 + 8];
            }
            // product-major issue: same-acc reuse distance = 6 MMAs
            mma16816b(acc[0][0], wahi[k16], bh0[0], bh1[0]);
            mma16816b(acc[0][1], wahi[k16], bh0[1], bh1[1]);
            mma16816b(acc[1][0], wahi[k16], bl0[0], bl1[0]);
            mma16816b(acc[1][1], wahi[k16], bl0[1], bl1[1]);
            mma16816b(acc[2][0], walo[k16], bh0[0], bh1[0]);
            mma16816b(acc[2][1], walo[k16], bh0[1], bh1[1]);
        }

        // ---- scatter summed C fragments to gfin[batch][row] ----
        {
            const int row0 = wid * 16 + gg;
#pragma unroll
            for (int nt = 0; nt < 2; ++nt) {
                const int bb = nt * 8 + t2;
                float s0 = acc[0][nt][0] + acc[1][nt][0] + acc[2][nt][0];
                float s1 = acc[0][nt][1] + acc[1][nt][1] + acc[2][nt][1];
                float s2 = acc[0][nt][2] + acc[1][nt][2] + acc[2][nt][2];
                float s3 = acc[0][nt][3] + acc[1][nt][3] + acc[2][nt][3];
                gfin[bb * GFS + row0]           = s0;
                gfin[(bb + 1) * GFS + row0]     = s1;
                gfin[bb * GFS + row0 + 8]       = s2;
                gfin[(bb + 1) * GFS + row0 + 8] = s3;
            }
        }
        __syncthreads();

        // ---- cell update: gates = gfin + cns ----
        {
            float2 vi = *(const float2*)&gfin[ub * GFS +       cc];
            float2 vf = *(const float2*)&gfin[ub * GFS +  32 + cc];
            float2 vg = *(const float2*)&gfin[ub * GFS +  64 + cc];
            float2 vo = *(const float2*)&gfin[ub * GFS +  96 + cc];
            float2 ci_ = *(const float2*)&cns[ub * GFS +       cc];
            float2 cf_ = *(const float2*)&cns[ub * GFS +  32 + cc];
            float2 cg_ = *(const float2*)&cns[ub * GFS +  64 + cc];
            float2 co_ = *(const float2*)&cns[ub * GFS +  96 + cc];

            float ig = fast_sig (vi.x + ci_.x);
            float fg = fast_sig (vf.x + cf_.x);
            float gv = fast_tanh(vg.x + cg_.x);
            float og = fast_sig (vo.x + co_.x);
            c0 = fg * c0 + ig * gv;
            float h0 = og * fast_tanh(c0);

            float ig1 = fast_sig (vi.y + ci_.y);
            float fg1 = fast_sig (vf.y + cf_.y);
            float gv1 = fast_tanh(vg.y + cg_.y);
            float og1 = fast_sig (vo.y + co_.y);
            c1 = fg1 * c1 + ig1 * gv1;
            float h1 = og1 * fast_tanh(c1);

            size_t m = (size_t)brow * TSTEPS + t;
            *(float2*)&dec_out[m * HD + col0] = make_float2(h0, h1);

            uint32_t phi, plo;
            split_bf2(h0, h1, phi, plo);
            *(uint32_t*)&g_hsp_hi[(t + 1) & 1][brow * HD + col0] = phi;
            *(uint32_t*)&g_hsp_lo[(t + 1) & 1][brow * HD + col0] = plo;
            *(uint32_t*)&g_Ahi[m * HD + col0] = phi;
            *(uint32_t*)&g_Alo[m * HD + col0] = plo;
        }

        // ---- per-group barrier: 8 monotone flags, tight acquire poll ----
        __syncthreads();
        if (tid == 0) {
            asm volatile("st.release.gpu.global.b32 [%0], %1;"
                         :: "l"(&g_done[blockIdx.x]), "r"(t + 1) : "memory");
        }
        if (tid < 8) {
            const int* fl = &g_done[(bg << 3) + tid];
            int v;
            do {
                asm volatile("ld.acquire.gpu.global.b32 %0, [%1];" : "=r"(v) : "l"(fl));
            } while (v <= t);
        }
        __syncthreads();
    }
}

// ============================================================
// Kernel 3: warp-MMA projection — product-major issue order
// ============================================================
#define PROJ_THREADS 256

__device__ __forceinline__ uint32_t sw_off(int row, int chunk) {
    return ((uint32_t)row * 8u + (uint32_t)(chunk ^ (row & 7))) * 16u;
}
__device__ __forceinline__ void ldm_x4(uint32_t addr, uint32_t* f) {
    asm volatile("ldmatrix.sync.aligned.m8n8.x4.shared.b16 {%0,%1,%2,%3}, [%4];"
                 : "=r"(f[0]), "=r"(f[1]), "=r"(f[2]), "=r"(f[3]) : "r"(addr));
}
__device__ __forceinline__ void ldm_x2(uint32_t addr, uint32_t* f) {
    asm volatile("ldmatrix.sync.aligned.m8n8.x2.shared.b16 {%0,%1}, [%2];"
                 : "=r"(f[0]), "=r"(f[1]) : "r"(addr));
}

__global__ void __launch_bounds__(PROJ_THREADS, 1)
proj_mma_kernel(const float* __restrict__ br, float* __restrict__ outp) {
    __shared__ __align__(16) __nv_bfloat16 sAh[MT * 64];
    __shared__ __align__(16) __nv_bfloat16 sAl[MT * 64];
    __shared__ __align__(16) __nv_bfloat16 sBh[NT * 64];
    __shared__ __align__(16) __nv_bfloat16 sBl[NT * 64];

    const int tid = threadIdx.x;
    const int wid = tid >> 5;
    const int lid = tid & 31;
    const int warp_m = wid & 3;
    const int warp_n = wid >> 2;
    const int ntile = blockIdx.x;
    const int mtile = blockIdx.y;
    const size_t gm0 = (size_t)mtile * MT;
    const int gn0 = ntile * NT;

    uint32_t sAh_b, sAl_b, sBh_b, sBl_b;
    {
        uint64_t t;
        asm("cvta.to.shared.u64 %0, %1;" : "=l"(t) : "l"((void*)sAh)); sAh_b = (uint32_t)t;
        asm("cvta.to.shared.u64 %0, %1;" : "=l"(t) : "l"((void*)sAl)); sAl_b = (uint32_t)t;
        asm("cvta.to.shared.u64 %0, %1;" : "=l"(t) : "l"((void*)sBh)); sBh_b = (uint32_t)t;
        asm("cvta.to.shared.u64 %0, %1;" : "=l"(t) : "l"((void*)sBl)); sBl_b = (uint32_t)t;
    }

    float acc[2][4][4];
#pragma unroll
    for (int i = 0; i < 2; ++i)
#pragma unroll
        for (int j = 0; j < 4; ++j)
#pragma unroll
            for (int q = 0; q < 4; ++q) acc[i][j][q] = 0.f;

    for (int kb = 0; kb < HD / 64; ++kb) {
        const int k0 = kb * 64;
        __syncthreads();
#pragma unroll
        for (int i = 0; i < (MT * 8) / PROJ_THREADS; ++i) {
            int idx = tid + i * PROJ_THREADS;
            int row = idx >> 3, ch = idx & 7;
            int4 vh = *(const int4*)&g_Ahi[(gm0 + row) * HD + k0 + ch * 8];
            int4 vl = *(const int4*)&g_Alo[(gm0 + row) * HD + k0 + ch * 8];
            *(int4*)((char*)sAh + sw_off(row, ch)) = vh;
            *(int4*)((char*)sAl + sw_off(row, ch)) = vl;
        }
#pragma unroll
        for (int i = 0; i < (NT * 8) / PROJ_THREADS; ++i) {
            int idx = tid + i * PROJ_THREADS;
            int row = idx >> 3, ch = idx & 7;
            int4 vh = *(const int4*)&g_Bhi[(size_t)(gn0 + row) * HD + k0 + ch * 8];
            int4 vl = *(const int4*)&g_Blo[(size_t)(gn0 + row) * HD + k0 + ch * 8];
            *(int4*)((char*)sBh + sw_off(row, ch)) = vh;
            *(int4*)((char*)sBl + sw_off(row, ch)) = vl;
        }
        __syncthreads();

#pragma unroll
        for (int k16 = 0; k16 < 4; ++k16) {
            uint32_t ah[2][4], al[2][4];
#pragma unroll
            for (int mt = 0; mt < 2; ++mt) {
                int row = warp_m * 32 + mt * 16 + (lid & 15);
                int ch  = k16 * 2 + (lid >> 4);
                ldm_x4(sAh_b + sw_off(row, ch), ah[mt]);
                ldm_x4(sAl_b + sw_off(row, ch), al[mt]);
            }
            uint32_t bh[4][2], bl[4][2];
#pragma unroll
            for (int nt = 0; nt < 4; ++nt) {
                int row = warp_n * 32 + nt * 8 + (lid & 7);
                int ch  = k16 * 2 + ((lid >> 3) & 1);
                ldm_x2(sBh_b + sw_off(row, ch), bh[nt]);
                ldm_x2(sBl_b + sw_off(row, ch), bl[nt]);
            }
            // product-major: same-acc reuse distance = 8 MMAs
#pragma unroll
            for (int mt = 0; mt < 2; ++mt)
#pragma unroll
                for (int nt = 0; nt < 4; ++nt)
                    mma16816(acc[mt][nt], ah[mt], bh[nt]);
#pragma unroll
            for (int mt = 0; mt < 2; ++mt)
#pragma unroll
                for (int nt = 0; nt < 4; ++nt)
                    mma16816(acc[mt][nt], ah[mt], bl[nt]);
#pragma unroll
            for (int mt = 0; mt < 2; ++mt)
#pragma unroll
                for (int nt = 0; nt < 4; ++nt)
                    mma16816(acc[mt][nt], al[mt], bh[nt]);
        }
    }

#pragma unroll
    for (int mt = 0; mt < 2; ++mt) {
#pragma unroll
        for (int nt = 0; nt < 4; ++nt) {
            int gn = gn0 + warp_n * 32 + nt * 8 + (lid & 3) * 2;
            if (gn < OUTD) {
                float2 bias = *(const float2*)&br[gn];
                size_t m = gm0 + warp_m * 32 + mt * 16 + (lid >> 2);
                float2 v0 = make_float2(acc[mt][nt][0] + bias.x,
                                        acc[mt][nt][1] + bias.y);
                float2 v1 = make_float2(acc[mt][nt][2] + bias.x,
                                        acc[mt][nt][3] + bias.y);
                *(float2*)&outp[m * OUTD + gn] = v0;
                *(float2*)&outp[(m + 8) * OUTD + gn] = v1;
            }
        }
    }
}

// ============================================================
extern "C" void kernel_launch(void* const* d_in, const int* in_sizes, int n_in,
                              void* d_out, int out_size) {
    const float* embed = (const float*)d_in[0];
    const float* W_ih  = (const float*)d_in[1];
    const float* W_hh  = (const float*)d_in[2];
    const float* b_ih  = (const float*)d_in[3];
    const float* b_hh  = (const float*)d_in[4];
    const float* W_rec = (const float*)d_in[5];
    const float* b_rec = (const float*)d_in[6];

    float* recon = (float*)d_out;                  // [B,T,OUT]
    float* dec   = recon + REC_ELEMS;              // [B,T,H]

    dim3 cgrid(BATCH / 64, G4 / 64);
    precompute_kernel<<<cgrid, 256>>>(embed, W_ih, b_ih, b_hh);
    convert_wrec_kernel<<<OUTP, 256>>>(W_rec);
    lstm_kernel<<<RGRID, RTHREADS>>>(W_ih, W_hh, dec);
    dim3 pgrid(NNT, NMT);
    proj_mma_kernel<<<pgrid, PROJ_THREADS>>>(b_rec, recon);
}

// round 11
// speedup vs baseline: 1.2743x; 1.2743x over previous
#include <cuda_runtime.h>
#include <cuda_bf16.h>
#include <math.h>
#include <stdint.h>

// Problem constants
#define BATCH 256
#define HD    256
#define G4    1024
#define TSTEPS 512
#define OUTD  702
#define OUTP  704           // padded to 11*64

#define NBG 16
#define NSL 8
#define BB  16
#define RGRID (NBG*NSL)     // 128
#define RTHREADS 256

#define REC_ELEMS ((size_t)BATCH*TSTEPS*OUTD)

// proj tiling
#define MROWS (BATCH*TSTEPS)            // 131072
#define MT    128
#define NT    64
#define NMT   (MROWS/MT)                // 1024
#define NNT   (OUTP/NT)                 // 11

#define GFS   132                       // gfin/cns padded stride
#define HSS   264                       // smem h padded stride (bf16)

// -------- device scratch (no allocations allowed) --------
__device__ __align__(16) float g_const[BATCH * G4];
// split-bf16 row-major images for the MMA projection
__device__ __align__(16) __nv_bfloat16 g_Ahi[(size_t)MROWS * HD];   // 64MB
__device__ __align__(16) __nv_bfloat16 g_Alo[(size_t)MROWS * HD];   // 64MB
__device__ __align__(16) __nv_bfloat16 g_Bhi[(size_t)OUTP * HD];
__device__ __align__(16) __nv_bfloat16 g_Blo[(size_t)OUTP * HD];

__device__ __forceinline__ float fast_tanh(float x) {
    float y;
    asm("tanh.approx.f32 %0, %1;" : "=f"(y) : "f"(x));
    return y;
}
__device__ __forceinline__ float fast_sig(float x) {
    return fmaf(fast_tanh(0.5f * x), 0.5f, 0.5f);
}
__device__ __forceinline__ void split_bf2(float x, float y, uint32_t& hi, uint32_t& lo) {
    __nv_bfloat16 xh = __float2bfloat16(x);
    __nv_bfloat16 yh = __float2bfloat16(y);
    __nv_bfloat16 xl = __float2bfloat16(x - __bfloat162float(xh));
    __nv_bfloat16 yl = __float2bfloat16(y - __bfloat162float(yh));
    __nv_bfloat162 ph; ph.x = xh; ph.y = yh;
    __nv_bfloat162 pl; pl.x = xl; pl.y = yl;
    hi = *(uint32_t*)&ph;
    lo = *(uint32_t*)&pl;
}
__device__ __forceinline__ uint32_t smem_u32p(const void* p) {
    uint32_t a;
    asm("{ .reg .u64 t; cvta.to.shared.u64 t, %1; cvt.u32.u64 %0, t; }"
        : "=r"(a) : "l"(p));
    return a;
}

__device__ __forceinline__ void mma16816(float* c, const uint32_t* a, const uint32_t* b) {
    asm volatile(
        "mma.sync.aligned.m16n8k16.row.col.f32.bf16.bf16.f32 "
        "{%0,%1,%2,%3}, {%4,%5,%6,%7}, {%8,%9}, {%0,%1,%2,%3};"
        : "+f"(c[0]), "+f"(c[1]), "+f"(c[2]), "+f"(c[3])
        : "r"(a[0]), "r"(a[1]), "r"(a[2]), "r"(a[3]), "r"(b[0]), "r"(b[1]));
}
__device__ __forceinline__ void mma16816b(float* c, const uint32_t* a, uint32_t b0, uint32_t b1) {
    asm volatile(
        "mma.sync.aligned.m16n8k16.row.col.f32.bf16.bf16.f32 "
        "{%0,%1,%2,%3}, {%4,%5,%6,%7}, {%8,%9}, {%0,%1,%2,%3};"
        : "+f"(c[0]), "+f"(c[1]), "+f"(c[2]), "+f"(c[3])
        : "r"(a[0]), "r"(a[1]), "r"(a[2]), "r"(a[3]), "r"(b0), "r"(b1));
}

// ============================================================
// Kernel 1: precompute const gates (tiled GEMM)
// ============================================================
__global__ void precompute_kernel(const float* __restrict__ embed,
                                  const float* __restrict__ W_ih,
                                  const float* __restrict__ b_ih,
                                  const float* __restrict__ b_hh) {
    __shared__ float As[16][64];
    __shared__ float Bs[16][64];
    const int tid = threadIdx.x;
    const int m0 = blockIdx.x * 64;
    const int n0 = blockIdx.y * 64;
    const int tx = tid & 15, ty = tid >> 4;
    const int lm = tid >> 2;
    const int lk = (tid & 3) * 4;

    float acc[4][4];
#pragma unroll
    for (int i = 0; i < 4; ++i)
#pragma unroll
        for (int j = 0; j < 4; ++j) acc[i][j] = 0.f;

    for (int k0 = 0; k0 < HD; k0 += 16) {
        float4 av = *(const float4*)&embed[(size_t)(m0 + lm) * HD + k0 + lk];
        float4 bv = *(const float4*)&W_ih[(size_t)(n0 + lm) * HD + k0 + lk];
        As[lk + 0][lm] = av.x; As[lk + 1][lm] = av.y;
        As[lk + 2][lm] = av.z; As[lk + 3][lm] = av.w;
        Bs[lk + 0][lm] = bv.x; Bs[lk + 1][lm] = bv.y;
        Bs[lk + 2][lm] = bv.z; Bs[lk + 3][lm] = bv.w;
        __syncthreads();
#pragma unroll
        for (int k = 0; k < 16; ++k) {
            float4 a = *(const float4*)&As[k][ty * 4];
            float4 b = *(const float4*)&Bs[k][tx * 4];
            acc[0][0] = fmaf(a.x, b.x, acc[0][0]); acc[0][1] = fmaf(a.x, b.y, acc[0][1]);
            acc[0][2] = fmaf(a.x, b.z, acc[0][2]); acc[0][3] = fmaf(a.x, b.w, acc[0][3]);
            acc[1][0] = fmaf(a.y, b.x, acc[1][0]); acc[1][1] = fmaf(a.y, b.y, acc[1][1]);
            acc[1][2] = fmaf(a.y, b.z, acc[1][2]); acc[1][3] = fmaf(a.y, b.w, acc[1][3]);
            acc[2][0] = fmaf(a.z, b.x, acc[2][0]); acc[2][1] = fmaf(a.z, b.y, acc[2][1]);
            acc[2][2] = fmaf(a.z, b.z, acc[2][2]); acc[2][3] = fmaf(a.z, b.w, acc[2][3]);
            acc[3][0] = fmaf(a.w, b.x, acc[3][0]); acc[3][1] = fmaf(a.w, b.y, acc[3][1]);
            acc[3][2] = fmaf(a.w, b.z, acc[3][2]); acc[3][3] = fmaf(a.w, b.w, acc[3][3]);
        }
        __syncthreads();
    }
#pragma unroll
    for (int i = 0; i < 4; ++i) {
        int b = m0 + ty * 4 + i;
#pragma unroll
        for (int j = 0; j < 4; ++j) {
            int row = n0 + tx * 4 + j;
            g_const[(size_t)b * G4 + row] = acc[i][j] + b_ih[row] + b_hh[row];
        }
    }
}

// ============================================================
// Kernel 1b: W_rec -> split-bf16 row-major images
// ============================================================
__global__ void convert_wrec_kernel(const float* __restrict__ Wr) {
    int n = blockIdx.x;
    int k = threadIdx.x;
    float v = (n < OUTD) ? Wr[(size_t)n * HD + k] : 0.f;
    __nv_bfloat16 hi = __float2bfloat16(v);
    __nv_bfloat16 lo = __float2bfloat16(v - __bfloat162float(hi));
    g_Bhi[(size_t)n * HD + k] = hi;
    g_Blo[(size_t)n * HD + k] = lo;
}

// ============================================================
// Kernel 2: persistent LSTM on tensor cores, cluster-of-8
// h exchanged by DSMEM push into all peers' ping-pong smem;
// one barrier.cluster per step (no global round trip, no flags)
// ============================================================
__global__ void __launch_bounds__(RTHREADS, 1) __cluster_dims__(NSL, 1, 1)
lstm_kernel(const float* __restrict__ W_ih,
            const float* __restrict__ W_hh,
            float* __restrict__ dec_out) {
    const int bg  = blockIdx.x >> 3;
    const int sl  = blockIdx.x & 7;      // == cluster ctarank
    const int tid = threadIdx.x;
    const int wid = tid >> 5;
    const int lid = tid & 31;

    __shared__ __align__(16) __nv_bfloat16 h_hi[2][BB * HSS];   // 16.9 KB
    __shared__ __align__(16) __nv_bfloat16 h_lo[2][BB * HSS];   // 16.9 KB
    __shared__ float gfin[BB * GFS];
    __shared__ float cns[BB * GFS];

    // ---- weight A-fragments in registers ----
    const int gg = lid >> 2;
    const int t2 = (lid & 3) * 2;
    uint32_t wahi[16][4], walo[16][4];
    {
        const int lr[2] = { wid * 16 + gg, wid * 16 + gg + 8 };
        int grow[2];
#pragma unroll
        for (int rr = 0; rr < 2; ++rr)
            grow[rr] = (lr[rr] >> 5) * 256 + sl * 32 + (lr[rr] & 31);
#pragma unroll
        for (int k16 = 0; k16 < 16; ++k16) {
#pragma unroll
            for (int kk = 0; kk < 2; ++kk) {
                int col = k16 * 16 + t2 + kk * 8;
#pragma unroll
                for (int rr = 0; rr < 2; ++rr) {
                    float2 a = *(const float2*)&W_ih[(size_t)grow[rr] * HD + col];
                    float2 b = *(const float2*)&W_hh[(size_t)grow[rr] * HD + col];
                    split_bf2(a.x + b.x, a.y + b.y,
                              wahi[k16][kk * 2 + rr], walo[k16][kk * 2 + rr]);
                }
            }
        }
    }

    for (int idx = tid; idx < BB * 128; idx += RTHREADS) {
        int b  = idx >> 7;
        int rr = idx & 127;
        int gr = (rr >> 5) * 256 + sl * 32 + (rr & 31);
        cns[b * GFS + rr] = g_const[(bg * BB + b) * G4 + gr];
    }

    // zero ping buffer (read at t=0)
    for (int idx = tid; idx < (BB * HSS) / 8; idx += RTHREADS) {
        ((uint4*)h_hi[0])[idx] = make_uint4(0, 0, 0, 0);
        ((uint4*)h_lo[0])[idx] = make_uint4(0, 0, 0, 0);
    }

    const int ub = tid >> 4;
    const int cc = (tid & 15) * 2;
    const int brow = bg * BB + ub;
    const int col0 = sl * 32 + cc;
    float c0 = 0.f, c1 = 0.f;

    // local smem addresses of this thread's h slot in both ping-pong bufs
    const uint32_t slot_hi[2] = {
        smem_u32p(&h_hi[0][ub * HSS + col0]), smem_u32p(&h_hi[1][ub * HSS + col0]) };
    const uint32_t slot_lo[2] = {
        smem_u32p(&h_lo[0][ub * HSS + col0]), smem_u32p(&h_lo[1][ub * HSS + col0]) };

    __syncthreads();
    // all peers' buffers initialized before anyone pushes into them
    asm volatile("barrier.cluster.arrive.aligned;" ::: "memory");
    asm volatile("barrier.cluster.wait.aligned;" ::: "memory");

    for (int t = 0; t < TSTEPS; ++t) {
        const __nv_bfloat16* hb_hi = h_hi[t & 1];
        const __nv_bfloat16* hb_lo = h_lo[t & 1];

        // ---- tensor-core gates: 3 separate product accumulators ----
        float acc[3][2][4];
#pragma unroll
        for (int p = 0; p < 3; ++p)
#pragma unroll
            for (int nt = 0; nt < 2; ++nt)
#pragma unroll
                for (int q = 0; q < 4; ++q) acc[p][nt][q] = 0.f;

#pragma unroll
        for (int k16 = 0; k16 < 16; ++k16) {
            const int k0 = k16 * 16 + t2;
            uint32_t bh0[2], bh1[2], bl0[2], bl1[2];
#pragma unroll
            for (int nt = 0; nt < 2; ++nt) {
                const int n = nt * 8 + gg;
                bh0[nt] = *(const uint32_t*)&hb_hi[n * HSS + k0];
                bh1[nt] = *(const uint32_t*)&hb_hi[n * HSS + k0 + 8];
                bl0[nt] = *(const uint32_t*)&hb_lo[n * HSS + k0];
                bl1[nt] = *(const uint32_t*)&hb_lo[n * HSS + k0 + 8];
            }
            mma16816b(acc[0][0], wahi[k16], bh0[0], bh1[0]);
            mma16816b(acc[0][1], wahi[k16], bh0[1], bh1[1]);
            mma16816b(acc[1][0], wahi[k16], bl0[0], bl1[0]);
            mma16816b(acc[1][1], wahi[k16], bl0[1], bl1[1]);
            mma16816b(acc[2][0], walo[k16], bh0[0], bh1[0]);
            mma16816b(acc[2][1], walo[k16], bh0[1], bh1[1]);
        }

        // ---- scatter summed C fragments to gfin[batch][row] ----
        {
            const int row0 = wid * 16 + gg;
#pragma unroll
            for (int nt = 0; nt < 2; ++nt) {
                const int bb = nt * 8 + t2;
                gfin[bb * GFS + row0]           = acc[0][nt][0] + acc[1][nt][0] + acc[2][nt][0];
                gfin[(bb + 1) * GFS + row0]     = acc[0][nt][1] + acc[1][nt][1] + acc[2][nt][1];
                gfin[bb * GFS + row0 + 8]       = acc[0][nt][2] + acc[1][nt][2] + acc[2][nt][2];
                gfin[(bb + 1) * GFS + row0 + 8] = acc[0][nt][3] + acc[1][nt][3] + acc[2][nt][3];
            }
        }
        __syncthreads();

        // ---- cell update + DSMEM push of h to all 8 cluster CTAs ----
        {
            float2 vi = *(const float2*)&gfin[ub * GFS +       cc];
            float2 vf = *(const float2*)&gfin[ub * GFS +  32 + cc];
            float2 vg = *(const float2*)&gfin[ub * GFS +  64 + cc];
            float2 vo = *(const float2*)&gfin[ub * GFS +  96 + cc];
            float2 ci_ = *(const float2*)&cns[ub * GFS +       cc];
            float2 cf_ = *(const float2*)&cns[ub * GFS +  32 + cc];
            float2 cg_ = *(const float2*)&cns[ub * GFS +  64 + cc];
            float2 co_ = *(const float2*)&cns[ub * GFS +  96 + cc];

            float ig = fast_sig (vi.x + ci_.x);
            float fg = fast_sig (vf.x + cf_.x);
            float gv = fast_tanh(vg.x + cg_.x);
            float og = fast_sig (vo.x + co_.x);
            c0 = fg * c0 + ig * gv;
            float h0 = og * fast_tanh(c0);

            float ig1 = fast_sig (vi.y + ci_.y);
            float fg1 = fast_sig (vf.y + cf_.y);
            float gv1 = fast_tanh(vg.y + cg_.y);
            float og1 = fast_sig (vo.y + co_.y);
            c1 = fg1 * c1 + ig1 * gv1;
            float h1 = og1 * fast_tanh(c1);

            size_t m = (size_t)brow * TSTEPS + t;
            *(float2*)&dec_out[m * HD + col0] = make_float2(h0, h1);

            uint32_t phi, plo;
            split_bf2(h0, h1, phi, plo);
            *(uint32_t*)&g_Ahi[m * HD + col0] = phi;
            *(uint32_t*)&g_Alo[m * HD + col0] = plo;

            const uint32_t lhi = slot_hi[(t + 1) & 1];
            const uint32_t llo = slot_lo[(t + 1) & 1];
#pragma unroll
            for (int rr = 0; rr < NSL; ++rr) {
                uint32_t pa, pb;
                asm("mapa.shared::cluster.u32 %0, %1, %2;" : "=r"(pa) : "r"(lhi), "r"(rr));
                asm("mapa.shared::cluster.u32 %0, %1, %2;" : "=r"(pb) : "r"(llo), "r"(rr));
                asm volatile("st.shared::cluster.u32 [%0], %1;" :: "r"(pa), "r"(phi) : "memory");
                asm volatile("st.shared::cluster.u32 [%0], %1;" :: "r"(pb), "r"(plo) : "memory");
            }
        }

        // ---- cluster barrier: orders DSMEM pushes, releases step t ----
        asm volatile("barrier.cluster.arrive.aligned;" ::: "memory");
        asm volatile("barrier.cluster.wait.aligned;" ::: "memory");
    }
}

// ============================================================
// Kernel 3: warp-MMA projection (R9 structure, measured 487us)
// ============================================================
#define PROJ_THREADS 256

__device__ __forceinline__ uint32_t sw_off(int row, int chunk) {
    return ((uint32_t)row * 8u + (uint32_t)(chunk ^ (row & 7))) * 16u;
}
__device__ __forceinline__ void ldm_x4(uint32_t addr, uint32_t* f) {
    asm volatile("ldmatrix.sync.aligned.m8n8.x4.shared.b16 {%0,%1,%2,%3}, [%4];"
                 : "=r"(f[0]), "=r"(f[1]), "=r"(f[2]), "=r"(f[3]) : "r"(addr));
}
__device__ __forceinline__ void ldm_x2(uint32_t addr, uint32_t* f) {
    asm volatile("ldmatrix.sync.aligned.m8n8.x2.shared.b16 {%0,%1}, [%2];"
                 : "=r"(f[0]), "=r"(f[1]) : "r"(addr));
}

__global__ void __launch_bounds__(PROJ_THREADS, 1)
proj_mma_kernel(const float* __restrict__ br, float* __restrict__ outp) {
    __shared__ __align__(16) __nv_bfloat16 sAh[MT * 64];
    __shared__ __align__(16) __nv_bfloat16 sAl[MT * 64];
    __shared__ __align__(16) __nv_bfloat16 sBh[NT * 64];
    __shared__ __align__(16) __nv_bfloat16 sBl[NT * 64];

    const int tid = threadIdx.x;
    const int wid = tid >> 5;
    const int lid = tid & 31;
    const int warp_m = wid & 3;
    const int warp_n = wid >> 2;
    const int ntile = blockIdx.x;
    const int mtile = blockIdx.y;
    const size_t gm0 = (size_t)mtile * MT;
    const int gn0 = ntile * NT;

    uint32_t sAh_b, sAl_b, sBh_b, sBl_b;
    {
        uint64_t t;
        asm("cvta.to.shared.u64 %0, %1;" : "=l"(t) : "l"((void*)sAh)); sAh_b = (uint32_t)t;
        asm("cvta.to.shared.u64 %0, %1;" : "=l"(t) : "l"((void*)sAl)); sAl_b = (uint32_t)t;
        asm("cvta.to.shared.u64 %0, %1;" : "=l"(t) : "l"((void*)sBh)); sBh_b = (uint32_t)t;
        asm("cvta.to.shared.u64 %0, %1;" : "=l"(t) : "l"((void*)sBl)); sBl_b = (uint32_t)t;
    }

    float acc[2][4][4];
#pragma unroll
    for (int i = 0; i < 2; ++i)
#pragma unroll
        for (int j = 0; j < 4; ++j)
#pragma unroll
            for (int q = 0; q < 4; ++q) acc[i][j][q] = 0.f;

    for (int kb = 0; kb < HD / 64; ++kb) {
        const int k0 = kb * 64;
        __syncthreads();
#pragma unroll
        for (int i = 0; i < (MT * 8) / PROJ_THREADS; ++i) {
            int idx = tid + i * PROJ_THREADS;
            int row = idx >> 3, ch = idx & 7;
            int4 vh = *(const int4*)&g_Ahi[(gm0 + row) * HD + k0 + ch * 8];
            int4 vl = *(const int4*)&g_Alo[(gm0 + row) * HD + k0 + ch * 8];
            *(int4*)((char*)sAh + sw_off(row, ch)) = vh;
            *(int4*)((char*)sAl + sw_off(row, ch)) = vl;
        }
#pragma unroll
        for (int i = 0; i < (NT * 8) / PROJ_THREADS; ++i) {
            int idx = tid + i * PROJ_THREADS;
            int row = idx >> 3, ch = idx & 7;
            int4 vh = *(const int4*)&g_Bhi[(size_t)(gn0 + row) * HD + k0 + ch * 8];
            int4 vl = *(const int4*)&g_Blo[(size_t)(gn0 + row) * HD + k0 + ch * 8];
            *(int4*)((char*)sBh + sw_off(row, ch)) = vh;
            *(int4*)((char*)sBl + sw_off(row, ch)) = vl;
        }
        __syncthreads();

#pragma unroll
        for (int k16 = 0; k16 < 4; ++k16) {
            uint32_t ah[2][4], al[2][4];
#pragma unroll
            for (int mt = 0; mt < 2; ++mt) {
                int row = warp_m * 32 + mt * 16 + (lid & 15);
                int ch  = k16 * 2 + (lid >> 4);
                ldm_x4(sAh_b + sw_off(row, ch), ah[mt]);
                ldm_x4(sAl_b + sw_off(row, ch), al[mt]);
            }
            uint32_t bh[4][2], bl[4][2];
#pragma unroll
            for (int nt = 0; nt < 4; ++nt) {
                int row = warp_n * 32 + nt * 8 + (lid & 7);
                int ch  = k16 * 2 + ((lid >> 3) & 1);
                ldm_x2(sBh_b + sw_off(row, ch), bh[nt]);
                ldm_x2(sBl_b + sw_off(row, ch), bl[nt]);
            }
#pragma unroll
            for (int mt = 0; mt < 2; ++mt)
#pragma unroll
                for (int nt = 0; nt < 4; ++nt)
                    mma16816(acc[mt][nt], ah[mt], bh[nt]);
#pragma unroll
            for (int mt = 0; mt < 2; ++mt)
#pragma unroll
                for (int nt = 0; nt < 4; ++nt)
                    mma16816(acc[mt][nt], ah[mt], bl[nt]);
#pragma unroll
            for (int mt = 0; mt < 2; ++mt)
#pragma unroll
                for (int nt = 0; nt < 4; ++nt)
                    mma16816(acc[mt][nt], al[mt], bh[nt]);
        }
    }

#pragma unroll
    for (int mt = 0; mt < 2; ++mt) {
#pragma unroll
        for (int nt = 0; nt < 4; ++nt) {
            int gn = gn0 + warp_n * 32 + nt * 8 + (lid & 3) * 2;
            if (gn < OUTD) {
                float2 bias = *(const float2*)&br[gn];
                size_t m = gm0 + warp_m * 32 + mt * 16 + (lid >> 2);
                float2 v0 = make_float2(acc[mt][nt][0] + bias.x,
                                        acc[mt][nt][1] + bias.y);
                float2 v1 = make_float2(acc[mt][nt][2] + bias.x,
                                        acc[mt][nt][3] + bias.y);
                *(float2*)&outp[m * OUTD + gn] = v0;
                *(float2*)&outp[(m + 8) * OUTD + gn] = v1;
            }
        }
    }
}

// ============================================================
extern "C" void kernel_launch(void* const* d_in, const int* in_sizes, int n_in,
                              void* d_out, int out_size) {
    const float* embed = (const float*)d_in[0];
    const float* W_ih  = (const float*)d_in[1];
    const float* W_hh  = (const float*)d_in[2];
    const float* b_ih  = (const float*)d_in[3];
    const float* b_hh  = (const float*)d_in[4];
    const float* W_rec = (const float*)d_in[5];
    const float* b_rec = (const float*)d_in[6];

    float* recon = (float*)d_out;                  // [B,T,OUT]
    float* dec   = recon + REC_ELEMS;              // [B,T,H]

    dim3 cgrid(BATCH / 64, G4 / 64);
    precompute_kernel<<<cgrid, 256>>>(embed, W_ih, b_ih, b_hh);
    convert_wrec_kernel<<<OUTP, 256>>>(W_rec);
    lstm_kernel<<<RGRID, RTHREADS>>>(W_ih, W_hh, dec);
    dim3 pgrid(NNT, NMT);
    proj_mma_kernel<<<pgrid, PROJ_THREADS>>>(b_rec, recon);
}

// round 12
// speedup vs baseline: 1.3070x; 1.0257x over previous
#include <cuda_runtime.h>
#include <cuda_bf16.h>
#include <math.h>
#include <stdint.h>

// Problem constants
#define BATCH 256
#define HD    256
#define G4    1024
#define TSTEPS 512
#define OUTD  702
#define OUTP  704           // padded to 11*64

#define NBG 16
#define NSL 8
#define BB  16
#define RGRID (NBG*NSL)     // 128
#define RTHREADS 256

#define REC_ELEMS ((size_t)BATCH*TSTEPS*OUTD)

// proj tiling
#define MROWS (BATCH*TSTEPS)            // 131072
#define MT    128
#define NT    64
#define NMT   (MROWS/MT)                // 1024
#define NNT   (OUTP/NT)                 // 11

#define GFS   132                       // gfin/cns padded stride
#define HSS   264                       // smem h padded stride (bf16)

// -------- device scratch (no allocations allowed) --------
__device__ __align__(16) float g_const[BATCH * G4];
// split-bf16 row-major images for the MMA projection
__device__ __align__(16) __nv_bfloat16 g_Ahi[(size_t)MROWS * HD];   // 64MB
__device__ __align__(16) __nv_bfloat16 g_Alo[(size_t)MROWS * HD];   // 64MB
__device__ __align__(16) __nv_bfloat16 g_Bhi[(size_t)OUTP * HD];
__device__ __align__(16) __nv_bfloat16 g_Blo[(size_t)OUTP * HD];

__device__ __forceinline__ float fast_tanh(float x) {
    float y;
    asm("tanh.approx.f32 %0, %1;" : "=f"(y) : "f"(x));
    return y;
}
__device__ __forceinline__ float fast_sig(float x) {
    return fmaf(fast_tanh(0.5f * x), 0.5f, 0.5f);
}
__device__ __forceinline__ void split_bf2(float x, float y, uint32_t& hi, uint32_t& lo) {
    __nv_bfloat16 xh = __float2bfloat16(x);
    __nv_bfloat16 yh = __float2bfloat16(y);
    __nv_bfloat16 xl = __float2bfloat16(x - __bfloat162float(xh));
    __nv_bfloat16 yl = __float2bfloat16(y - __bfloat162float(yh));
    __nv_bfloat162 ph; ph.x = xh; ph.y = yh;
    __nv_bfloat162 pl; pl.x = xl; pl.y = yl;
    hi = *(uint32_t*)&ph;
    lo = *(uint32_t*)&pl;
}
__device__ __forceinline__ uint32_t smem_u32p(const void* p) {
    uint32_t a;
    asm("{ .reg .u64 t; cvta.to.shared.u64 t, %1; cvt.u32.u64 %0, t; }"
        : "=r"(a) : "l"(p));
    return a;
}

__device__ __forceinline__ void mma16816(float* c, const uint32_t* a, const uint32_t* b) {
    asm volatile(
        "mma.sync.aligned.m16n8k16.row.col.f32.bf16.bf16.f32 "
        "{%0,%1,%2,%3}, {%4,%5,%6,%7}, {%8,%9}, {%0,%1,%2,%3};"
        : "+f"(c[0]), "+f"(c[1]), "+f"(c[2]), "+f"(c[3])
        : "r"(a[0]), "r"(a[1]), "r"(a[2]), "r"(a[3]), "r"(b[0]), "r"(b[1]));
}
__device__ __forceinline__ void mma16816b(float* c, const uint32_t* a, uint32_t b0, uint32_t b1) {
    asm volatile(
        "mma.sync.aligned.m16n8k16.row.col.f32.bf16.bf16.f32 "
        "{%0,%1,%2,%3}, {%4,%5,%6,%7}, {%8,%9}, {%0,%1,%2,%3};"
        : "+f"(c[0]), "+f"(c[1]), "+f"(c[2]), "+f"(c[3])
        : "r"(a[0]), "r"(a[1]), "r"(a[2]), "r"(a[3]), "r"(b0), "r"(b1));
}

// ============================================================
// Kernel 1: precompute const gates (tiled GEMM)
// ============================================================
__global__ void precompute_kernel(const float* __restrict__ embed,
                                  const float* __restrict__ W_ih,
                                  const float* __restrict__ b_ih,
                                  const float* __restrict__ b_hh) {
    __shared__ float As[16][64];
    __shared__ float Bs[16][64];
    const int tid = threadIdx.x;
    const int m0 = blockIdx.x * 64;
    const int n0 = blockIdx.y * 64;
    const int tx = tid & 15, ty = tid >> 4;
    const int lm = tid >> 2;
    const int lk = (tid & 3) * 4;

    float acc[4][4];
#pragma unroll
    for (int i = 0; i < 4; ++i)
#pragma unroll
        for (int j = 0; j < 4; ++j) acc[i][j] = 0.f;

    for (int k0 = 0; k0 < HD; k0 += 16) {
        float4 av = *(const float4*)&embed[(size_t)(m0 + lm) * HD + k0 + lk];
        float4 bv = *(const float4*)&W_ih[(size_t)(n0 + lm) * HD + k0 + lk];
        As[lk + 0][lm] = av.x; As[lk + 1][lm] = av.y;
        As[lk + 2][lm] = av.z; As[lk + 3][lm] = av.w;
        Bs[lk + 0][lm] = bv.x; Bs[lk + 1][lm] = bv.y;
        Bs[lk + 2][lm] = bv.z; Bs[lk + 3][lm] = bv.w;
        __syncthreads();
#pragma unroll
        for (int k = 0; k < 16; ++k) {
            float4 a = *(const float4*)&As[k][ty * 4];
            float4 b = *(const float4*)&Bs[k][tx * 4];
            acc[0][0] = fmaf(a.x, b.x, acc[0][0]); acc[0][1] = fmaf(a.x, b.y, acc[0][1]);
            acc[0][2] = fmaf(a.x, b.z, acc[0][2]); acc[0][3] = fmaf(a.x, b.w, acc[0][3]);
            acc[1][0] = fmaf(a.y, b.x, acc[1][0]); acc[1][1] = fmaf(a.y, b.y, acc[1][1]);
            acc[1][2] = fmaf(a.y, b.z, acc[1][2]); acc[1][3] = fmaf(a.y, b.w, acc[1][3]);
            acc[2][0] = fmaf(a.z, b.x, acc[2][0]); acc[2][1] = fmaf(a.z, b.y, acc[2][1]);
            acc[2][2] = fmaf(a.z, b.z, acc[2][2]); acc[2][3] = fmaf(a.z, b.w, acc[2][3]);
            acc[3][0] = fmaf(a.w, b.x, acc[3][0]); acc[3][1] = fmaf(a.w, b.y, acc[3][1]);
            acc[3][2] = fmaf(a.w, b.z, acc[3][2]); acc[3][3] = fmaf(a.w, b.w, acc[3][3]);
        }
        __syncthreads();
    }
#pragma unroll
    for (int i = 0; i < 4; ++i) {
        int b = m0 + ty * 4 + i;
#pragma unroll
        for (int j = 0; j < 4; ++j) {
            int row = n0 + tx * 4 + j;
            g_const[(size_t)b * G4 + row] = acc[i][j] + b_ih[row] + b_hh[row];
        }
    }
}

// ============================================================
// Kernel 1b: W_rec -> split-bf16 row-major images
// ============================================================
__global__ void convert_wrec_kernel(const float* __restrict__ Wr) {
    int n = blockIdx.x;
    int k = threadIdx.x;
    float v = (n < OUTD) ? Wr[(size_t)n * HD + k] : 0.f;
    __nv_bfloat16 hi = __float2bfloat16(v);
    __nv_bfloat16 lo = __float2bfloat16(v - __bfloat162float(hi));
    g_Bhi[(size_t)n * HD + k] = hi;
    g_Blo[(size_t)n * HD + k] = lo;
}

// ============================================================
// Kernel 2: persistent LSTM on tensor cores, cluster-of-8
// DSMEM push exchange; global STGs hidden between cluster
// barrier arrive and wait
// ============================================================
__global__ void __launch_bounds__(RTHREADS, 1) __cluster_dims__(NSL, 1, 1)
lstm_kernel(const float* __restrict__ W_ih,
            const float* __restrict__ W_hh,
            float* __restrict__ dec_out) {
    const int bg  = blockIdx.x >> 3;
    const int sl  = blockIdx.x & 7;      // == cluster ctarank
    const int tid = threadIdx.x;
    const int wid = tid >> 5;
    const int lid = tid & 31;

    __shared__ __align__(16) __nv_bfloat16 h_hi[2][BB * HSS];
    __shared__ __align__(16) __nv_bfloat16 h_lo[2][BB * HSS];
    __shared__ float gfin[BB * GFS];
    __shared__ float cns[BB * GFS];

    // ---- weight A-fragments in registers ----
    const int gg = lid >> 2;
    const int t2 = (lid & 3) * 2;
    uint32_t wahi[16][4], walo[16][4];
    {
        const int lr[2] = { wid * 16 + gg, wid * 16 + gg + 8 };
        int grow[2];
#pragma unroll
        for (int rr = 0; rr < 2; ++rr)
            grow[rr] = (lr[rr] >> 5) * 256 + sl * 32 + (lr[rr] & 31);
#pragma unroll
        for (int k16 = 0; k16 < 16; ++k16) {
#pragma unroll
            for (int kk = 0; kk < 2; ++kk) {
                int col = k16 * 16 + t2 + kk * 8;
#pragma unroll
                for (int rr = 0; rr < 2; ++rr) {
                    float2 a = *(const float2*)&W_ih[(size_t)grow[rr] * HD + col];
                    float2 b = *(const float2*)&W_hh[(size_t)grow[rr] * HD + col];
                    split_bf2(a.x + b.x, a.y + b.y,
                              wahi[k16][kk * 2 + rr], walo[k16][kk * 2 + rr]);
                }
            }
        }
    }

    for (int idx = tid; idx < BB * 128; idx += RTHREADS) {
        int b  = idx >> 7;
        int rr = idx & 127;
        int gr = (rr >> 5) * 256 + sl * 32 + (rr & 31);
        cns[b * GFS + rr] = g_const[(bg * BB + b) * G4 + gr];
    }

    // zero ping buffer (read at t=0)
    for (int idx = tid; idx < (BB * HSS) / 8; idx += RTHREADS) {
        ((uint4*)h_hi[0])[idx] = make_uint4(0, 0, 0, 0);
        ((uint4*)h_lo[0])[idx] = make_uint4(0, 0, 0, 0);
    }

    const int ub = tid >> 4;
    const int cc = (tid & 15) * 2;
    const int brow = bg * BB + ub;
    const int col0 = sl * 32 + cc;
    float c0 = 0.f, c1 = 0.f;

    const uint32_t slot_hi[2] = {
        smem_u32p(&h_hi[0][ub * HSS + col0]), smem_u32p(&h_hi[1][ub * HSS + col0]) };
    const uint32_t slot_lo[2] = {
        smem_u32p(&h_lo[0][ub * HSS + col0]), smem_u32p(&h_lo[1][ub * HSS + col0]) };

    __syncthreads();
    asm volatile("barrier.cluster.arrive.aligned;" ::: "memory");
    asm volatile("barrier.cluster.wait.aligned;" ::: "memory");

    for (int t = 0; t < TSTEPS; ++t) {
        const __nv_bfloat16* hb_hi = h_hi[t & 1];
        const __nv_bfloat16* hb_lo = h_lo[t & 1];

        // ---- tensor-core gates: 3 separate product accumulators ----
        float acc[3][2][4];
#pragma unroll
        for (int p = 0; p < 3; ++p)
#pragma unroll
            for (int nt = 0; nt < 2; ++nt)
#pragma unroll
                for (int q = 0; q < 4; ++q) acc[p][nt][q] = 0.f;

#pragma unroll
        for (int k16 = 0; k16 < 16; ++k16) {
            const int k0 = k16 * 16 + t2;
            uint32_t bh0[2], bh1[2], bl0[2], bl1[2];
#pragma unroll
            for (int nt = 0; nt < 2; ++nt) {
                const int n = nt * 8 + gg;
                bh0[nt] = *(const uint32_t*)&hb_hi[n * HSS + k0];
                bh1[nt] = *(const uint32_t*)&hb_hi[n * HSS + k0 + 8];
                bl0[nt] = *(const uint32_t*)&hb_lo[n * HSS + k0];
                bl1[nt] = *(const uint32_t*)&hb_lo[n * HSS + k0 + 8];
            }
            mma16816b(acc[0][0], wahi[k16], bh0[0], bh1[0]);
            mma16816b(acc[0][1], wahi[k16], bh0[1], bh1[1]);
            mma16816b(acc[1][0], wahi[k16], bl0[0], bl1[0]);
            mma16816b(acc[1][1], wahi[k16], bl0[1], bl1[1]);
            mma16816b(acc[2][0], walo[k16], bh0[0], bh1[0]);
            mma16816b(acc[2][1], walo[k16], bh0[1], bh1[1]);
        }

        // ---- scatter summed C fragments to gfin[batch][row] ----
        {
            const int row0 = wid * 16 + gg;
#pragma unroll
            for (int nt = 0; nt < 2; ++nt) {
                const int bb = nt * 8 + t2;
                gfin[bb * GFS + row0]           = acc[0][nt][0] + acc[1][nt][0] + acc[2][nt][0];
                gfin[(bb + 1) * GFS + row0]     = acc[0][nt][1] + acc[1][nt][1] + acc[2][nt][1];
                gfin[bb * GFS + row0 + 8]       = acc[0][nt][2] + acc[1][nt][2] + acc[2][nt][2];
                gfin[(bb + 1) * GFS + row0 + 8] = acc[0][nt][3] + acc[1][nt][3] + acc[2][nt][3];
            }
        }
        __syncthreads();

        // ---- cell update, DSMEM push, then STGs inside barrier window ----
        float h0, h1;
        uint32_t phi, plo;
        {
            float2 vi = *(const float2*)&gfin[ub * GFS +       cc];
            float2 vf = *(const float2*)&gfin[ub * GFS +  32 + cc];
            float2 vg = *(const float2*)&gfin[ub * GFS +  64 + cc];
            float2 vo = *(const float2*)&gfin[ub * GFS +  96 + cc];
            float2 ci_ = *(const float2*)&cns[ub * GFS +       cc];
            float2 cf_ = *(const float2*)&cns[ub * GFS +  32 + cc];
            float2 cg_ = *(const float2*)&cns[ub * GFS +  64 + cc];
            float2 co_ = *(const float2*)&cns[ub * GFS +  96 + cc];

            float ig = fast_sig (vi.x + ci_.x);
            float fg = fast_sig (vf.x + cf_.x);
            float gv = fast_tanh(vg.x + cg_.x);
            float og = fast_sig (vo.x + co_.x);
            c0 = fg * c0 + ig * gv;
            h0 = og * fast_tanh(c0);

            float ig1 = fast_sig (vi.y + ci_.y);
            float fg1 = fast_sig (vf.y + cf_.y);
            float gv1 = fast_tanh(vg.y + cg_.y);
            float og1 = fast_sig (vo.y + co_.y);
            c1 = fg1 * c1 + ig1 * gv1;
            h1 = og1 * fast_tanh(c1);

            split_bf2(h0, h1, phi, plo);

            const uint32_t lhi = slot_hi[(t + 1) & 1];
            const uint32_t llo = slot_lo[(t + 1) & 1];
#pragma unroll
            for (int rr = 0; rr < NSL; ++rr) {
                uint32_t pa, pb;
                asm("mapa.shared::cluster.u32 %0, %1, %2;" : "=r"(pa) : "r"(lhi), "r"(rr));
                asm("mapa.shared::cluster.u32 %0, %1, %2;" : "=r"(pb) : "r"(llo), "r"(rr));
                asm volatile("st.shared::cluster.u32 [%0], %1;" :: "r"(pa), "r"(phi) : "memory");
                asm volatile("st.shared::cluster.u32 [%0], %1;" :: "r"(pb), "r"(plo) : "memory");
            }
        }

        // arrive (orders the DSMEM pushes), then fire-and-forget global
        // stores while peers drain, then wait
        asm volatile("barrier.cluster.arrive.aligned;" ::: "memory");
        {
            size_t m = (size_t)brow * TSTEPS + t;
            *(float2*)&dec_out[m * HD + col0] = make_float2(h0, h1);
            *(uint32_t*)&g_Ahi[m * HD + col0] = phi;
            *(uint32_t*)&g_Alo[m * HD + col0] = plo;
        }
        asm volatile("barrier.cluster.wait.aligned;" ::: "memory");
    }
}

// ============================================================
// Kernel 3: warp-MMA projection — 4 warps/CTA, warp tile 64x32
// (3 MMAs per ldmatrix vs 2 before: -33% L1 traffic)
// ============================================================
#define PROJ_THREADS 128

__device__ __forceinline__ uint32_t sw_off(int row, int chunk) {
    return ((uint32_t)row * 8u + (uint32_t)(chunk ^ (row & 7))) * 16u;
}
__device__ __forceinline__ void ldm_x4(uint32_t addr, uint32_t* f) {
    asm volatile("ldmatrix.sync.aligned.m8n8.x4.shared.b16 {%0,%1,%2,%3}, [%4];"
                 : "=r"(f[0]), "=r"(f[1]), "=r"(f[2]), "=r"(f[3]) : "r"(addr));
}
__device__ __forceinline__ void ldm_x2(uint32_t addr, uint32_t* f) {
    asm volatile("ldmatrix.sync.aligned.m8n8.x2.shared.b16 {%0,%1}, [%2];"
                 : "=r"(f[0]), "=r"(f[1]) : "r"(addr));
}

__global__ void __launch_bounds__(PROJ_THREADS, 3)
proj_mma_kernel(const float* __restrict__ br, float* __restrict__ outp) {
    __shared__ __align__(16) __nv_bfloat16 sAh[MT * 64];
    __shared__ __align__(16) __nv_bfloat16 sAl[MT * 64];
    __shared__ __align__(16) __nv_bfloat16 sBh[NT * 64];
    __shared__ __align__(16) __nv_bfloat16 sBl[NT * 64];

    const int tid = threadIdx.x;
    const int wid = tid >> 5;
    const int lid = tid & 31;
    const int warp_m = wid & 1;          // 2 x m64
    const int warp_n = wid >> 1;         // 2 x n32
    const int ntile = blockIdx.x;
    const int mtile = blockIdx.y;
    const size_t gm0 = (size_t)mtile * MT;
    const int gn0 = ntile * NT;

    uint32_t sAh_b, sAl_b, sBh_b, sBl_b;
    {
        uint64_t t;
        asm("cvta.to.shared.u64 %0, %1;" : "=l"(t) : "l"((void*)sAh)); sAh_b = (uint32_t)t;
        asm("cvta.to.shared.u64 %0, %1;" : "=l"(t) : "l"((void*)sAl)); sAl_b = (uint32_t)t;
        asm("cvta.to.shared.u64 %0, %1;" : "=l"(t) : "l"((void*)sBh)); sBh_b = (uint32_t)t;
        asm("cvta.to.shared.u64 %0, %1;" : "=l"(t) : "l"((void*)sBl)); sBl_b = (uint32_t)t;
    }

    float acc[4][4][4];                  // [mt][nt][quad]
#pragma unroll
    for (int i = 0; i < 4; ++i)
#pragma unroll
        for (int j = 0; j < 4; ++j)
#pragma unroll
            for (int q = 0; q < 4; ++q) acc[i][j][q] = 0.f;

    for (int kb = 0; kb < HD / 64; ++kb) {
        const int k0 = kb * 64;
        __syncthreads();
#pragma unroll
        for (int i = 0; i < (MT * 8) / PROJ_THREADS; ++i) {
            int idx = tid + i * PROJ_THREADS;
            int row = idx >> 3, ch = idx & 7;
            int4 vh = *(const int4*)&g_Ahi[(gm0 + row) * HD + k0 + ch * 8];
            int4 vl = *(const int4*)&g_Alo[(gm0 + row) * HD + k0 + ch * 8];
            *(int4*)((char*)sAh + sw_off(row, ch)) = vh;
            *(int4*)((char*)sAl + sw_off(row, ch)) = vl;
        }
#pragma unroll
        for (int i = 0; i < (NT * 8) / PROJ_THREADS; ++i) {
            int idx = tid + i * PROJ_THREADS;
            int row = idx >> 3, ch = idx & 7;
            int4 vh = *(const int4*)&g_Bhi[(size_t)(gn0 + row) * HD + k0 + ch * 8];
            int4 vl = *(const int4*)&g_Blo[(size_t)(gn0 + row) * HD + k0 + ch * 8];
            *(int4*)((char*)sBh + sw_off(row, ch)) = vh;
            *(int4*)((char*)sBl + sw_off(row, ch)) = vl;
        }
        __syncthreads();

#pragma unroll
        for (int k16 = 0; k16 < 4; ++k16) {
            uint32_t ah[4][4], al[4][4];
#pragma unroll
            for (int mt = 0; mt < 4; ++mt) {
                int row = warp_m * 64 + mt * 16 + (lid & 15);
                int ch  = k16 * 2 + (lid >> 4);
                ldm_x4(sAh_b + sw_off(row, ch), ah[mt]);
                ldm_x4(sAl_b + sw_off(row, ch), al[mt]);
            }
            uint32_t bh[4][2], bl[4][2];
#pragma unroll
            for (int nt = 0; nt < 4; ++nt) {
                int row = warp_n * 32 + nt * 8 + (lid & 7);
                int ch  = k16 * 2 + ((lid >> 3) & 1);
                ldm_x2(sBh_b + sw_off(row, ch), bh[nt]);
                ldm_x2(sBl_b + sw_off(row, ch), bl[nt]);
            }
#pragma unroll
            for (int mt = 0; mt < 4; ++mt)
#pragma unroll
                for (int nt = 0; nt < 4; ++nt)
                    mma16816(acc[mt][nt], ah[mt], bh[nt]);
#pragma unroll
            for (int mt = 0; mt < 4; ++mt)
#pragma unroll
                for (int nt = 0; nt < 4; ++nt)
                    mma16816(acc[mt][nt], ah[mt], bl[nt]);
#pragma unroll
            for (int mt = 0; mt < 4; ++mt)
#pragma unroll
                for (int nt = 0; nt < 4; ++nt)
                    mma16816(acc[mt][nt], al[mt], bh[nt]);
        }
    }

#pragma unroll
    for (int mt = 0; mt < 4; ++mt) {
#pragma unroll
        for (int nt = 0; nt < 4; ++nt) {
            int gn = gn0 + warp_n * 32 + nt * 8 + (lid & 3) * 2;
            if (gn < OUTD) {
                float2 bias = *(const float2*)&br[gn];
                size_t m = gm0 + warp_m * 64 + mt * 16 + (lid >> 2);
                float2 v0 = make_float2(acc[mt][nt][0] + bias.x,
                                        acc[mt][nt][1] + bias.y);
                float2 v1 = make_float2(acc[mt][nt][2] + bias.x,
                                        acc[mt][nt][3] + bias.y);
                *(float2*)&outp[m * OUTD + gn] = v0;
                *(float2*)&outp[(m + 8) * OUTD + gn] = v1;
            }
        }
    }
}

// ============================================================
extern "C" void kernel_launch(void* const* d_in, const int* in_sizes, int n_in,
                              void* d_out, int out_size) {
    const float* embed = (const float*)d_in[0];
    const float* W_ih  = (const float*)d_in[1];
    const float* W_hh  = (const float*)d_in[2];
    const float* b_ih  = (const float*)d_in[3];
    const float* b_hh  = (const float*)d_in[4];
    const float* W_rec = (const float*)d_in[5];
    const float* b_rec = (const float*)d_in[6];

    float* recon = (float*)d_out;                  // [B,T,OUT]
    float* dec   = recon + REC_ELEMS;              // [B,T,H]

    dim3 cgrid(BATCH / 64, G4 / 64);
    precompute_kernel<<<cgrid, 256>>>(embed, W_ih, b_ih, b_hh);
    convert_wrec_kernel<<<OUTP, 256>>>(W_rec);
    lstm_kernel<<<RGRID, RTHREADS>>>(W_ih, W_hh, dec);
    dim3 pgrid(NNT, NMT);
    proj_mma_kernel<<<pgrid, PROJ_THREADS>>>(b_rec, recon);
}